// round 2
// baseline (speedup 1.0000x reference)
#include <cuda_runtime.h>

// FullAttention: causal MHA, B=2, L=2048, H=16, E=D=64, fp32.
// queries/keys/values: [B, L, H, E], output: [B, L, H, E].
// Flash-attention-2 style SIMT fp32 kernel:
//   grid = (L/BM, B*H), block = 256 threads.
//   Each CTA: 64 query rows of one (b,h); iterates causal key tiles of 64.
//   Thread (ty,tx) (16x16 grid) owns a 4x4 register tile of S and of O.
//   Smem: Q^T [E][64] (pre-scaled), K^T [E][64], V [64][E], P^T [64][68].

#define B_   2
#define L_   2048
#define H_   16
#define E_   64
#define BM   64
#define BN   64
#define NTH  256
#define PS_STRIDE 68   // 68 floats: float4-aligned, 16B bank shift per row

#define SMEM_FLOATS (E_*BM + E_*BN + BN*E_ + BN*PS_STRIDE)
#define SMEM_BYTES  (SMEM_FLOATS * 4)

__device__ __forceinline__ float neg_inf() { return __int_as_float(0xff800000u); }

__global__ __launch_bounds__(NTH) void fa_kernel(
    const float* __restrict__ Q, const float* __restrict__ K,
    const float* __restrict__ V, float* __restrict__ O)
{
    extern __shared__ float sm[];
    float* Qs = sm;                    // [E_][BM]   transposed, pre-scaled
    float* Ks = Qs + E_ * BM;          // [E_][BN]   transposed
    float* Vs = Ks + E_ * BN;          // [BN][E_]   row-major
    float* Ps = Vs + BN * E_;          // [BN][PS_STRIDE]  P transposed (key-major)

    const int qtile = blockIdx.x;
    const int bh    = blockIdx.y;
    const int b     = bh >> 4;         // H_ = 16
    const int h     = bh & 15;
    const int m0    = qtile * BM;

    const int tid = threadIdx.x;
    const int tx  = tid & 15;          // 0..15 -> output cols tx*4..+3
    const int ty  = tid >> 4;          // 0..15 -> output rows ty*4..+3

    const float scale = 0.125f;        // 1/sqrt(64)

    // ---- Load Q tile, transposed into Qs[e][m], pre-scaled ----
    {
        const int m  = tid & 63;
        const int e0 = (tid >> 6) << 4;   // 0,16,32,48
        const float* qg = Q + (((size_t)b * L_ + (m0 + m)) * H_ + h) * E_ + e0;
        #pragma unroll
        for (int i = 0; i < 4; ++i) {
            float4 v = *(const float4*)(qg + i * 4);
            Qs[(e0 + i*4 + 0) * BM + m] = v.x * scale;
            Qs[(e0 + i*4 + 1) * BM + m] = v.y * scale;
            Qs[(e0 + i*4 + 2) * BM + m] = v.z * scale;
            Qs[(e0 + i*4 + 3) * BM + m] = v.w * scale;
        }
    }

    float acc[4][4];
    float mrow[4], lrow[4];
    #pragma unroll
    for (int r = 0; r < 4; ++r) {
        mrow[r] = neg_inf();
        lrow[r] = 0.0f;
        #pragma unroll
        for (int c = 0; c < 4; ++c) acc[r][c] = 0.0f;
    }

    for (int j = 0; j <= qtile; ++j) {
        const int n0 = j * BN;
        __syncthreads();   // previous iteration's Ps/Vs reads done; Qs visible on iter 0

        // ---- Load K tile (transposed) and V tile (row-major) ----
        {
            const int n  = tid & 63;
            const int e0 = (tid >> 6) << 4;
            const float* kg = K + (((size_t)b * L_ + (n0 + n)) * H_ + h) * E_ + e0;
            const float* vg = V + (((size_t)b * L_ + (n0 + n)) * H_ + h) * E_ + e0;
            #pragma unroll
            for (int i = 0; i < 4; ++i) {
                float4 kv = *(const float4*)(kg + i * 4);
                Ks[(e0 + i*4 + 0) * BN + n] = kv.x;
                Ks[(e0 + i*4 + 1) * BN + n] = kv.y;
                Ks[(e0 + i*4 + 2) * BN + n] = kv.z;
                Ks[(e0 + i*4 + 3) * BN + n] = kv.w;
                *(float4*)(Vs + n * E_ + e0 + i * 4) = *(const float4*)(vg + i * 4);
            }
        }
        __syncthreads();

        // ---- S = (scaled Q) K^T : 4x4 register tile ----
        float s[4][4];
        #pragma unroll
        for (int r = 0; r < 4; ++r)
            #pragma unroll
            for (int c = 0; c < 4; ++c) s[r][c] = 0.0f;

        #pragma unroll 8
        for (int e = 0; e < E_; ++e) {
            float4 qv = *(const float4*)(Qs + e * BM + ty * 4);
            float4 kv = *(const float4*)(Ks + e * BN + tx * 4);
            float qa[4] = {qv.x, qv.y, qv.z, qv.w};
            float ka[4] = {kv.x, kv.y, kv.z, kv.w};
            #pragma unroll
            for (int r = 0; r < 4; ++r)
                #pragma unroll
                for (int c = 0; c < 4; ++c)
                    s[r][c] = fmaf(qa[r], ka[c], s[r][c]);
        }

        // ---- causal mask on diagonal tile (m0 == n0) ----
        if (j == qtile) {
            #pragma unroll
            for (int r = 0; r < 4; ++r)
                #pragma unroll
                for (int c = 0; c < 4; ++c)
                    if (tx * 4 + c > ty * 4 + r) s[r][c] = neg_inf();
        }

        // ---- online softmax (row stats reduced over the 16 tx lanes) ----
        #pragma unroll
        for (int r = 0; r < 4; ++r) {
            float mx = fmaxf(fmaxf(s[r][0], s[r][1]), fmaxf(s[r][2], s[r][3]));
            #pragma unroll
            for (int off = 1; off < 16; off <<= 1)
                mx = fmaxf(mx, __shfl_xor_sync(0xffffffffu, mx, off));
            float mnew = fmaxf(mrow[r], mx);
            float corr = __expf(mrow[r] - mnew);
            mrow[r] = mnew;
            float rs = 0.0f;
            #pragma unroll
            for (int c = 0; c < 4; ++c) {
                float p = __expf(s[r][c] - mnew);
                s[r][c] = p;
                rs += p;
            }
            #pragma unroll
            for (int off = 1; off < 16; off <<= 1)
                rs += __shfl_xor_sync(0xffffffffu, rs, off);
            lrow[r] = lrow[r] * corr + rs;
            #pragma unroll
            for (int c = 0; c < 4; ++c) acc[r][c] *= corr;
        }

        // ---- write P transposed: Ps[n][m] (float4 of 4 consecutive rows) ----
        #pragma unroll
        for (int c = 0; c < 4; ++c) {
            float4 pv = make_float4(s[0][c], s[1][c], s[2][c], s[3][c]);
            *(float4*)(Ps + (tx * 4 + c) * PS_STRIDE + ty * 4) = pv;
        }
        __syncthreads();

        // ---- O += P V : k-loop over keys n ----
        #pragma unroll 4
        for (int n = 0; n < BN; ++n) {
            float4 p = *(const float4*)(Ps + n * PS_STRIDE + ty * 4);
            float4 v = *(const float4*)(Vs + n * E_ + tx * 4);
            float pa[4] = {p.x, p.y, p.z, p.w};
            float va[4] = {v.x, v.y, v.z, v.w};
            #pragma unroll
            for (int r = 0; r < 4; ++r)
                #pragma unroll
                for (int c = 0; c < 4; ++c)
                    acc[r][c] = fmaf(pa[r], va[c], acc[r][c]);
        }
    }

    // ---- epilogue: normalize and store ----
    #pragma unroll
    for (int r = 0; r < 4; ++r) {
        float inv = 1.0f / lrow[r];
        int m = m0 + ty * 4 + r;
        float4 o = make_float4(acc[r][0] * inv, acc[r][1] * inv,
                               acc[r][2] * inv, acc[r][3] * inv);
        *(float4*)(O + (((size_t)b * L_ + m) * H_ + h) * E_ + tx * 4) = o;
    }
}

extern "C" void kernel_launch(void* const* d_in, const int* in_sizes, int n_in,
                              void* d_out, int out_size)
{
    const float* Q = (const float*)d_in[0];
    const float* K = (const float*)d_in[1];
    const float* V = (const float*)d_in[2];
    float* O = (float*)d_out;

    cudaFuncSetAttribute(fa_kernel, cudaFuncAttributeMaxDynamicSharedMemorySize,
                         SMEM_BYTES);

    dim3 grid(L_ / BM, B_ * H_);
    fa_kernel<<<grid, NTH, SMEM_BYTES>>>(Q, K, V, O);
}

// round 5
// speedup vs baseline: 1.4264x; 1.4264x over previous
#include <cuda_runtime.h>

// FullAttention: causal MHA, B=2, L=2048, H=16, E=D=64, fp32.
// FA-2 SIMT kernel, R3: 128x128 tiles, 8x8 register tiles (crossbar-balanced
// 1 B/FMA), split-halves thread tiling for conflict-free float4 LDS.
// R3 fix: PSTR 68 -> 132 (P^T rows hold BM=128 entries; 68 overflowed smem).
//   grid = (L/128, B*H) = (16, 32), block = 256 threads (16x16).
//   Thread (ty,tx): S rows {ty*4+r, 64+ty*4+r}, S cols {tx*4+c, 64+tx*4+c},
//                   O rows same, O cols tx*4..+3.

#define B_   2
#define L_   2048
#define H_   16
#define E_   64
#define BM   128
#define BN   128
#define NTH  256
#define VSTR 68    // V row stride: 64 cols + pad (conflict-free float4 r/w)
#define PSTR 132   // P^T row stride: 128 cols + pad (2-way on stores only)

#define SMEM_FLOATS (E_*BM + E_*BN + BN*VSTR + BN*PSTR)
#define SMEM_BYTES  (SMEM_FLOATS * 4)

__device__ __forceinline__ float neg_inf() { return __int_as_float(0xff800000u); }

__global__ __launch_bounds__(NTH, 1) void fa_kernel(
    const float* __restrict__ Q, const float* __restrict__ K,
    const float* __restrict__ V, float* __restrict__ O)
{
    extern __shared__ float sm[];
    float* Qs = sm;                 // [E_][BM]  transposed, pre-scaled by scale*log2(e)
    float* Ks = Qs + E_ * BM;       // [E_][BN]  transposed
    float* Vs = Ks + E_ * BN;       // [BN][VSTR]
    float* Ps = Vs + BN * VSTR;     // [BN][PSTR]  P transposed (key-major)

    const int qtile = blockIdx.x;
    const int bh    = blockIdx.y;
    const int b     = bh >> 4;      // H_ = 16
    const int h     = bh & 15;
    const int m0    = qtile * BM;

    const int tid = threadIdx.x;
    const int tx  = tid & 15;
    const int ty  = tid >> 4;

    // scale * log2(e): softmax done in base-2
    const float scale2 = 0.125f * 1.4426950408889634f;

    // ---- Load Q tile, transposed into Qs[e][m], pre-scaled ----
    {
        const int m  = tid >> 1;          // 0..127
        const int e0 = (tid & 1) * 32;    // 0 or 32
        const float* qg = Q + (((size_t)b * L_ + (m0 + m)) * H_ + h) * E_ + e0;
        #pragma unroll
        for (int i = 0; i < 8; ++i) {
            float4 v = *(const float4*)(qg + i * 4);
            Qs[(e0 + i*4 + 0) * BM + m] = v.x * scale2;
            Qs[(e0 + i*4 + 1) * BM + m] = v.y * scale2;
            Qs[(e0 + i*4 + 2) * BM + m] = v.z * scale2;
            Qs[(e0 + i*4 + 3) * BM + m] = v.w * scale2;
        }
    }

    float acc[8][4];
    float mrow[8], lrow[8];
    #pragma unroll
    for (int r = 0; r < 8; ++r) {
        mrow[r] = neg_inf();
        lrow[r] = 0.0f;
        #pragma unroll
        for (int c = 0; c < 4; ++c) acc[r][c] = 0.0f;
    }

    for (int j = 0; j <= qtile; ++j) {
        const int n0 = j * BN;
        __syncthreads();   // prior iter's Ks/Vs/Ps reads done; Qs visible iter 0

        // ---- Load K tile (transposed) and V tile (row-major, padded) ----
        {
            const int n  = tid >> 1;
            const int e0 = (tid & 1) * 32;
            const float* kg = K + (((size_t)b * L_ + (n0 + n)) * H_ + h) * E_ + e0;
            const float* vg = V + (((size_t)b * L_ + (n0 + n)) * H_ + h) * E_ + e0;
            #pragma unroll
            for (int i = 0; i < 8; ++i) {
                float4 kv = *(const float4*)(kg + i * 4);
                Ks[(e0 + i*4 + 0) * BN + n] = kv.x;
                Ks[(e0 + i*4 + 1) * BN + n] = kv.y;
                Ks[(e0 + i*4 + 2) * BN + n] = kv.z;
                Ks[(e0 + i*4 + 3) * BN + n] = kv.w;
                *(float4*)(Vs + n * VSTR + e0 + i * 4) = *(const float4*)(vg + i * 4);
            }
        }
        __syncthreads();

        // ---- S = (scaled Q) K^T : 8x8 register tile (split halves) ----
        float s[8][8];
        #pragma unroll
        for (int r = 0; r < 8; ++r)
            #pragma unroll
            for (int c = 0; c < 8; ++c) s[r][c] = 0.0f;

        #pragma unroll 8
        for (int e = 0; e < E_; ++e) {
            float4 q0 = *(const float4*)(Qs + e * BM + ty * 4);
            float4 q1 = *(const float4*)(Qs + e * BM + 64 + ty * 4);
            float4 k0 = *(const float4*)(Ks + e * BN + tx * 4);
            float4 k1 = *(const float4*)(Ks + e * BN + 64 + tx * 4);
            float qa[8] = {q0.x, q0.y, q0.z, q0.w, q1.x, q1.y, q1.z, q1.w};
            float ka[8] = {k0.x, k0.y, k0.z, k0.w, k1.x, k1.y, k1.z, k1.w};
            #pragma unroll
            for (int r = 0; r < 8; ++r)
                #pragma unroll
                for (int c = 0; c < 8; ++c)
                    s[r][c] = fmaf(qa[r], ka[c], s[r][c]);
        }

        // ---- causal mask on diagonal tile ----
        if (j == qtile) {
            #pragma unroll
            for (int r = 0; r < 8; ++r) {
                const int rg = ((r >> 2) << 6) + ty * 4 + (r & 3);
                #pragma unroll
                for (int c = 0; c < 8; ++c) {
                    const int cg = ((c >> 2) << 6) + tx * 4 + (c & 3);
                    if (cg > rg) s[r][c] = neg_inf();
                }
            }
        }

        // ---- online softmax in base-2 (reduce over 16 tx lanes) ----
        #pragma unroll
        for (int r = 0; r < 8; ++r) {
            float mx = s[r][0];
            #pragma unroll
            for (int c = 1; c < 8; ++c) mx = fmaxf(mx, s[r][c]);
            #pragma unroll
            for (int off = 1; off < 16; off <<= 1)
                mx = fmaxf(mx, __shfl_xor_sync(0xffffffffu, mx, off));
            float mnew = fmaxf(mrow[r], mx);
            float corr = exp2f(mrow[r] - mnew);
            mrow[r] = mnew;
            float rs = 0.0f;
            #pragma unroll
            for (int c = 0; c < 8; ++c) {
                float p = exp2f(s[r][c] - mnew);
                s[r][c] = p;
                rs += p;
            }
            #pragma unroll
            for (int off = 1; off < 16; off <<= 1)
                rs += __shfl_xor_sync(0xffffffffu, rs, off);
            lrow[r] = lrow[r] * corr + rs;
            #pragma unroll
            for (int c = 0; c < 4; ++c) acc[r][c] *= corr;
        }

        // ---- write P transposed: Ps[n][m] (two float4 per owned column) ----
        #pragma unroll
        for (int c = 0; c < 8; ++c) {
            const int nloc = ((c >> 2) << 6) + tx * 4 + (c & 3);
            float4 p0 = make_float4(s[0][c], s[1][c], s[2][c], s[3][c]);
            float4 p1 = make_float4(s[4][c], s[5][c], s[6][c], s[7][c]);
            *(float4*)(Ps + nloc * PSTR + ty * 4)      = p0;
            *(float4*)(Ps + nloc * PSTR + 64 + ty * 4) = p1;
        }
        __syncthreads();

        // ---- O += P V ----
        #pragma unroll 4
        for (int n = 0; n < BN; ++n) {
            float4 p0 = *(const float4*)(Ps + n * PSTR + ty * 4);
            float4 p1 = *(const float4*)(Ps + n * PSTR + 64 + ty * 4);
            float4 v  = *(const float4*)(Vs + n * VSTR + tx * 4);
            float pa[8] = {p0.x, p0.y, p0.z, p0.w, p1.x, p1.y, p1.z, p1.w};
            float va[4] = {v.x, v.y, v.z, v.w};
            #pragma unroll
            for (int r = 0; r < 8; ++r)
                #pragma unroll
                for (int c = 0; c < 4; ++c)
                    acc[r][c] = fmaf(pa[r], va[c], acc[r][c]);
        }
    }

    // ---- epilogue: normalize and store ----
    #pragma unroll
    for (int r = 0; r < 8; ++r) {
        float inv = 1.0f / lrow[r];
        int m = m0 + ((r >> 2) << 6) + ty * 4 + (r & 3);
        float4 o = make_float4(acc[r][0] * inv, acc[r][1] * inv,
                               acc[r][2] * inv, acc[r][3] * inv);
        *(float4*)(O + (((size_t)b * L_ + m) * H_ + h) * E_ + tx * 4) = o;
    }
}

extern "C" void kernel_launch(void* const* d_in, const int* in_sizes, int n_in,
                              void* d_out, int out_size)
{
    const float* Q = (const float*)d_in[0];
    const float* K = (const float*)d_in[1];
    const float* V = (const float*)d_in[2];
    float* O = (float*)d_out;

    cudaFuncSetAttribute(fa_kernel, cudaFuncAttributeMaxDynamicSharedMemorySize,
                         SMEM_BYTES);

    dim3 grid(L_ / BM, B_ * H_);
    fa_kernel<<<grid, NTH, SMEM_BYTES>>>(Q, K, V, O);
}

// round 7
// speedup vs baseline: 3.6267x; 2.5425x over previous
#include <cuda_runtime.h>
#include <cstdint>

// FullAttention causal MHA, B=2, L=2048, H=16, E=D=64, fp32.
// R7: warp-level FA-2 on mma.sync.aligned.m16n8k8.tf32 (base PTX, no 'a' features).
//   grid=(16,32), 256 thr = 8 warps. Warp w owns q-rows [wid*16, wid*16+16) of a
//   128-row CTA tile; key tiles of 64. Q frags preloaded to regs; K, V^T staged
//   in smem (stride-68 pad, conflict-free fragment loads). S in registers;
//   P acc->A-frag via intra-quad shuffles. Online softmax per row pair.

#define B_   2
#define L_   2048
#define H_   16
#define E_   64
#define BM   128
#define BN   64
#define NTH  256
#define STR  68          // smem row stride (floats)

#define SMEM_FLOATS (BM*STR + BN*STR + E_*STR)
#define SMEM_BYTES  (SMEM_FLOATS * 4)

__device__ __forceinline__ float neg_inf() { return __int_as_float(0xff800000u); }

__device__ __forceinline__ uint32_t f2tf32(float x) {
    uint32_t r;
    asm("cvt.rna.tf32.f32 %0, %1;" : "=r"(r) : "f"(x));
    return r;
}

// D = A(16x8 tf32) * B(8x8 tf32) + C, row.col, fp32 acc. d may alias c.
__device__ __forceinline__ void mma8(float* d, const uint32_t* a,
                                     uint32_t b0, uint32_t b1, const float* c) {
    asm volatile(
        "mma.sync.aligned.m16n8k8.row.col.f32.tf32.tf32.f32 "
        "{%0,%1,%2,%3}, {%4,%5,%6,%7}, {%8,%9}, {%10,%11,%12,%13};"
        : "=f"(d[0]), "=f"(d[1]), "=f"(d[2]), "=f"(d[3])
        : "r"(a[0]), "r"(a[1]), "r"(a[2]), "r"(a[3]),
          "r"(b0), "r"(b1),
          "f"(c[0]), "f"(c[1]), "f"(c[2]), "f"(c[3]));
}

__global__ __launch_bounds__(NTH, 1) void fa_mma_kernel(
    const float* __restrict__ Q, const float* __restrict__ K,
    const float* __restrict__ V, float* __restrict__ O)
{
    extern __shared__ float sm[];
    float* Qs  = sm;                 // [BM][STR] tf32 bits (scaled)
    float* Ks  = Qs + BM * STR;      // [BN][STR] tf32 bits
    float* Vts = Ks + BN * STR;      // [E_][STR] V transposed: Vts[d][n], tf32 bits

    const int tid  = threadIdx.x;
    const int wid  = tid >> 5;
    const int lane = tid & 31;
    const int q4   = lane & 3;       // quad col id
    const int r0   = (wid << 4) + (lane >> 2);   // CTA-local row (first of pair)

    const int qtile = blockIdx.x;
    const int bh    = blockIdx.y;
    const int b     = bh >> 4;
    const int h     = bh & 15;
    const int m0    = qtile * BM;
    const int ntiles = 2 * (qtile + 1);

    const float scale2 = 0.125f * 1.4426950408889634f;  // 1/sqrt(64)*log2(e)

    // ---- stage Q (scaled, tf32-rounded) ----
    {
        const int m  = tid >> 1;
        const int e0 = (tid & 1) * 32;
        const float* qg = Q + (((size_t)b * L_ + (m0 + m)) * H_ + h) * E_ + e0;
        #pragma unroll
        for (int i = 0; i < 8; ++i) {
            float4 v = *(const float4*)(qg + i * 4);
            uint4 t;
            t.x = f2tf32(v.x * scale2); t.y = f2tf32(v.y * scale2);
            t.z = f2tf32(v.z * scale2); t.w = f2tf32(v.w * scale2);
            *(uint4*)(Qs + m * STR + e0 + i * 4) = t;
        }
    }
    __syncthreads();

    // ---- preload Q fragments: qf[kt][0..3] ----
    uint32_t qf[8][4];
    {
        const uint32_t* Qu = (const uint32_t*)Qs;
        #pragma unroll
        for (int kt = 0; kt < 8; ++kt) {
            qf[kt][0] = Qu[ r0      * STR + 8 * kt + q4    ];
            qf[kt][1] = Qu[(r0 + 8) * STR + 8 * kt + q4    ];
            qf[kt][2] = Qu[ r0      * STR + 8 * kt + q4 + 4];
            qf[kt][3] = Qu[(r0 + 8) * STR + 8 * kt + q4 + 4];
        }
    }

    float o[8][4];
    #pragma unroll
    for (int nt = 0; nt < 8; ++nt)
        #pragma unroll
        for (int u = 0; u < 4; ++u) o[nt][u] = 0.0f;
    float m0row = neg_inf(), m1row = neg_inf(), l0 = 0.0f, l1 = 0.0f;

    const int rowg0 = m0 + r0;
    const int rowg1 = rowg0 + 8;

    for (int j = 0; j < ntiles; ++j) {
        const int n0 = j * BN;
        __syncthreads();   // prev iter's Ks/Vts fragment reads complete

        // ---- stage K tile [64][64] and V^T tile [64][64] ----
        {
            const int n  = tid >> 2;
            const int e0 = (tid & 3) * 16;
            const float* kg = K + (((size_t)b * L_ + (n0 + n)) * H_ + h) * E_ + e0;
            const float* vg = V + (((size_t)b * L_ + (n0 + n)) * H_ + h) * E_ + e0;
            #pragma unroll
            for (int i = 0; i < 4; ++i) {
                float4 kv = *(const float4*)(kg + i * 4);
                uint4 t;
                t.x = f2tf32(kv.x); t.y = f2tf32(kv.y);
                t.z = f2tf32(kv.z); t.w = f2tf32(kv.w);
                *(uint4*)(Ks + n * STR + e0 + i * 4) = t;

                float4 vv = *(const float4*)(vg + i * 4);
                uint32_t tv[4] = { f2tf32(vv.x), f2tf32(vv.y), f2tf32(vv.z), f2tf32(vv.w) };
                #pragma unroll
                for (int c = 0; c < 4; ++c)
                    ((uint32_t*)Vts)[(e0 + i * 4 + c) * STR + n] = tv[c];
            }
        }
        __syncthreads();

        // ---- S = Q K^T : s[nt][4], rows {r0, r0+8}, cols {8nt+2q4, +1} ----
        float s[8][4];
        #pragma unroll
        for (int nt = 0; nt < 8; ++nt)
            #pragma unroll
            for (int u = 0; u < 4; ++u) s[nt][u] = 0.0f;

        const uint32_t* Ku = (const uint32_t*)Ks;
        #pragma unroll
        for (int kt = 0; kt < 8; ++kt) {
            #pragma unroll
            for (int nt = 0; nt < 8; ++nt) {
                uint32_t b0 = Ku[(8 * nt + (lane >> 2)) * STR + 8 * kt + q4];
                uint32_t b1 = Ku[(8 * nt + (lane >> 2)) * STR + 8 * kt + q4 + 4];
                mma8(s[nt], qf[kt], b0, b1, s[nt]);
            }
        }

        // ---- causal mask (only the two diagonal-adjacent tiles) ----
        if (j >= ntiles - 2) {
            #pragma unroll
            for (int nt = 0; nt < 8; ++nt) {
                #pragma unroll
                for (int u = 0; u < 2; ++u) {
                    int colg = n0 + 8 * nt + 2 * q4 + u;
                    if (colg > rowg0) s[nt][u]     = neg_inf();
                    if (colg > rowg1) s[nt][2 + u] = neg_inf();
                }
            }
        }

        // ---- online softmax (base 2), reduce within quad ----
        float mx0 = s[0][0], mx1 = s[0][2];
        #pragma unroll
        for (int nt = 0; nt < 8; ++nt) {
            mx0 = fmaxf(mx0, fmaxf(s[nt][0], s[nt][1]));
            mx1 = fmaxf(mx1, fmaxf(s[nt][2], s[nt][3]));
        }
        #pragma unroll
        for (int off = 1; off < 4; off <<= 1) {
            mx0 = fmaxf(mx0, __shfl_xor_sync(0xffffffffu, mx0, off));
            mx1 = fmaxf(mx1, __shfl_xor_sync(0xffffffffu, mx1, off));
        }
        float mn0 = fmaxf(m0row, mx0), mn1 = fmaxf(m1row, mx1);
        float c0 = exp2f(m0row - mn0), c1 = exp2f(m1row - mn1);
        m0row = mn0; m1row = mn1;

        float ts0 = 0.0f, ts1 = 0.0f;
        #pragma unroll
        for (int nt = 0; nt < 8; ++nt) {
            float p0 = exp2f(s[nt][0] - mn0);
            float p1 = exp2f(s[nt][1] - mn0);
            float p2 = exp2f(s[nt][2] - mn1);
            float p3 = exp2f(s[nt][3] - mn1);
            s[nt][0] = p0; s[nt][1] = p1; s[nt][2] = p2; s[nt][3] = p3;
            ts0 += p0 + p1; ts1 += p2 + p3;
        }
        #pragma unroll
        for (int off = 1; off < 4; off <<= 1) {
            ts0 += __shfl_xor_sync(0xffffffffu, ts0, off);
            ts1 += __shfl_xor_sync(0xffffffffu, ts1, off);
        }
        l0 = l0 * c0 + ts0;
        l1 = l1 * c1 + ts1;

        #pragma unroll
        for (int nt = 0; nt < 8; ++nt) {
            o[nt][0] *= c0; o[nt][1] *= c0;
            o[nt][2] *= c1; o[nt][3] *= c1;
        }

        // ---- O += P V : convert P acc->A frags via quad shuffles, mma ----
        const int src_lo = (lane & ~3) | (q4 >> 1);
        const int src_hi = src_lo + 2;
        const bool odd = (q4 & 1);
        const uint32_t* Vu = (const uint32_t*)Vts;
        #pragma unroll
        for (int kt = 0; kt < 8; ++kt) {
            float va, vb;
            uint32_t a[4];
            va = __shfl_sync(0xffffffffu, s[kt][0], src_lo);
            vb = __shfl_sync(0xffffffffu, s[kt][1], src_lo);
            a[0] = __float_as_uint(odd ? vb : va);
            va = __shfl_sync(0xffffffffu, s[kt][2], src_lo);
            vb = __shfl_sync(0xffffffffu, s[kt][3], src_lo);
            a[1] = __float_as_uint(odd ? vb : va);
            va = __shfl_sync(0xffffffffu, s[kt][0], src_hi);
            vb = __shfl_sync(0xffffffffu, s[kt][1], src_hi);
            a[2] = __float_as_uint(odd ? vb : va);
            va = __shfl_sync(0xffffffffu, s[kt][2], src_hi);
            vb = __shfl_sync(0xffffffffu, s[kt][3], src_hi);
            a[3] = __float_as_uint(odd ? vb : va);

            #pragma unroll
            for (int nt = 0; nt < 8; ++nt) {
                uint32_t b0 = Vu[(8 * nt + (lane >> 2)) * STR + 8 * kt + q4];
                uint32_t b1 = Vu[(8 * nt + (lane >> 2)) * STR + 8 * kt + q4 + 4];
                mma8(o[nt], a, b0, b1, o[nt]);
            }
        }
    }

    // ---- epilogue: normalize, store float2 per (row, nt) ----
    {
        float inv0 = 1.0f / l0, inv1 = 1.0f / l1;
        float* og0 = O + (((size_t)b * L_ + rowg0) * H_ + h) * E_;
        float* og1 = O + (((size_t)b * L_ + rowg1) * H_ + h) * E_;
        #pragma unroll
        for (int nt = 0; nt < 8; ++nt) {
            int col = 8 * nt + 2 * q4;
            *(float2*)(og0 + col) = make_float2(o[nt][0] * inv0, o[nt][1] * inv0);
            *(float2*)(og1 + col) = make_float2(o[nt][2] * inv1, o[nt][3] * inv1);
        }
    }
}

extern "C" void kernel_launch(void* const* d_in, const int* in_sizes, int n_in,
                              void* d_out, int out_size)
{
    const float* Q = (const float*)d_in[0];
    const float* K = (const float*)d_in[1];
    const float* V = (const float*)d_in[2];
    float* O = (float*)d_out;

    cudaFuncSetAttribute(fa_mma_kernel, cudaFuncAttributeMaxDynamicSharedMemorySize,
                         SMEM_BYTES);
    dim3 grid(L_ / BM, B_ * H_);
    fa_mma_kernel<<<grid, NTH, SMEM_BYTES>>>(Q, K, V, O);
}